// round 1
// baseline (speedup 1.0000x reference)
#include <cuda_runtime.h>
#include <math.h>

// Problem constants
#define LSEQ 8192
#define NFFT 16384          // 2*LSEQ, = 4^7
#define NQ   4096           // NFFT/4 butterflies per radix-4 stage
#define DM   768
#define EMB  33
#define FO   64
#define SHIFT_C 0.05f
#define FFT_THREADS 512
#define SMEM_BYTES ((NFFT + NQ) * (int)sizeof(float2))   // 160 KB

// ---------------- scratch (device globals: no allocations allowed) ----------
__device__ float  g_S[LSEQ * FO];        // 2 MB   post-MLP activations S3[l][f]
__device__ float  g_k[DM * LSEQ];        // 25 MB  filter k[d][l]
__device__ float2 g_Kf[(size_t)DM * NFFT]; // 100 MB scrambled spectrum per channel
__device__ float2 g_tw[NQ];              // 32 KB  twiddle table W_N^t, t<N/4

// ---------------- complex helpers ----------------
__device__ __forceinline__ float2 cadd(float2 a, float2 b){ return make_float2(a.x+b.x, a.y+b.y); }
__device__ __forceinline__ float2 csub(float2 a, float2 b){ return make_float2(a.x-b.x, a.y-b.y); }
__device__ __forceinline__ float2 cmul(float2 a, float2 b){
    return make_float2(a.x*b.x - a.y*b.y, a.x*b.y + a.y*b.x);
}

// ---------------- twiddle init (double-precision sincospi) ----------------
__global__ void twiddle_init_kernel() {
    int t = blockIdx.x * blockDim.x + threadIdx.x;
    if (t < NQ) {
        double s, c;
        sincospi(-2.0 * (double)t / (double)NFFT, &s, &c);
        g_tw[t] = make_float2((float)c, (float)s);
    }
}

// ---------------- radix-4 DIF forward: natural in -> scrambled out ----------
// W_4 = -i (forward).  y_r stored at idx + r*span, twiddled by W_M^{r j}, M=4*span.
__device__ __forceinline__ void fft4_fwd(float2* d, const float2* tw, int tid) {
    #pragma unroll
    for (int s = 6; s >= 0; s--) {
        const int ls   = 2 * s;
        const int span = 1 << ls;
        #pragma unroll 2
        for (int q = tid; q < NQ; q += FFT_THREADS) {
            const int j   = q & (span - 1);
            const int g   = q >> ls;
            const int idx = (g << (ls + 2)) + j;
            float2 x0 = d[idx];
            float2 x1 = d[idx + span];
            float2 x2 = d[idx + 2*span];
            float2 x3 = d[idx + 3*span];
            float2 t0 = cadd(x0, x2), t1 = csub(x0, x2);
            float2 t2 = cadd(x1, x3), t3 = csub(x1, x3);
            float2 mi_t3 = make_float2(t3.y, -t3.x);       // -i * t3
            float2 s0 = cadd(t0, t2);
            float2 s2 = csub(t0, t2);
            float2 s1 = cadd(t1, mi_t3);
            float2 s3 = csub(t1, mi_t3);
            float2 w1 = tw[j << (12 - ls)];                // W_M^j
            float2 w2 = cmul(w1, w1);                      // W_M^{2j}
            float2 w3 = cmul(w2, w1);                      // W_M^{3j}
            d[idx]          = s0;
            d[idx + span]   = cmul(s1, w1);
            d[idx + 2*span] = cmul(s2, w2);
            d[idx + 3*span] = cmul(s3, w3);
        }
        __syncthreads();
    }
}

// ---------------- radix-4 DIT inverse: scrambled in -> natural out ----------
// Exact inverse of fft4_fwd stage-by-stage (reversed order, conj twiddles,
// F4^{-1} = conj(F4)/4).  Net scale = 1/NFFT (matches circular-conv normalization).
__device__ __forceinline__ void fft4_inv(float2* d, const float2* tw, int tid) {
    #pragma unroll
    for (int s = 0; s <= 6; s++) {
        const int ls   = 2 * s;
        const int span = 1 << ls;
        #pragma unroll 2
        for (int q = tid; q < NQ; q += FFT_THREADS) {
            const int j   = q & (span - 1);
            const int g   = q >> ls;
            const int idx = (g << (ls + 2)) + j;
            float2 y0 = d[idx];
            float2 y1 = d[idx + span];
            float2 y2 = d[idx + 2*span];
            float2 y3 = d[idx + 3*span];
            float2 w1 = tw[j << (12 - ls)];
            float2 w1c = make_float2(w1.x, -w1.y);
            float2 w2c = cmul(w1c, w1c);
            float2 w3c = cmul(w2c, w1c);
            float2 z0 = y0;
            float2 z1 = cmul(y1, w1c);
            float2 z2 = cmul(y2, w2c);
            float2 z3 = cmul(y3, w3c);
            float2 t0 = cadd(z0, z2), t1 = csub(z0, z2);
            float2 t2 = cadd(z1, z3), t3 = csub(z1, z3);
            float2 it3 = make_float2(-t3.y, t3.x);          // +i * t3
            float2 u0 = cadd(t0, t2);
            float2 u1 = cadd(t1, it3);
            float2 u2 = csub(t0, t2);
            float2 u3 = csub(t1, it3);
            d[idx]          = make_float2(0.25f*u0.x, 0.25f*u0.y);
            d[idx + span]   = make_float2(0.25f*u1.x, 0.25f*u1.y);
            d[idx + 2*span] = make_float2(0.25f*u2.x, 0.25f*u2.y);
            d[idx + 3*span] = make_float2(0.25f*u3.x, 0.25f*u3.y);
        }
        __syncthreads();
    }
}

// ---------------- filter MLP stage 1-3: S3[l][f] -------------------------
// 4 positions per 256-thread block, 64 lanes per position.
__global__ void mlp_kernel(const float* __restrict__ z, const float* __restrict__ freq,
                           const float* __restrict__ W1, const float* __restrict__ b1,
                           const float* __restrict__ W2, const float* __restrict__ b2,
                           const float* __restrict__ W3, const float* __restrict__ b3) {
    __shared__ float zs[4][EMB];
    __shared__ float as[4][FO];
    __shared__ float bs[4][FO];
    const int tid = threadIdx.x;
    const int lg  = tid >> 6;
    const int f   = tid & 63;
    const int l   = blockIdx.x * 4 + lg;

    if (f < EMB) zs[lg][f] = z[l * EMB + f];
    __syncthreads();

    const float fr = freq[f];

    float acc = b1[f];
    #pragma unroll
    for (int e = 0; e < EMB; e++) acc += zs[lg][e] * W1[e * FO + f];
    as[lg][f] = sinf(fr * acc);
    __syncthreads();

    acc = b2[f];
    #pragma unroll
    for (int e = 0; e < FO; e++) acc += as[lg][e] * W2[e * FO + f];
    bs[lg][f] = sinf(fr * acc);
    __syncthreads();

    acc = b3[f];
    #pragma unroll
    for (int e = 0; e < FO; e++) acc += bs[lg][e] * W3[e * FO + f];
    g_S[l * FO + f] = sinf(fr * acc);
}

// ---------------- output projection + exponential modulation -> k[d][l] ----
// Tile: 32 l x 128 d per 256-thread block.
__global__ void filt_kernel(const float* __restrict__ Wout, const float* __restrict__ t,
                            const float* __restrict__ deltas) {
    __shared__ float Ss[32][FO];     // 8 KB
    __shared__ float Ws[FO][128];    // 32 KB
    const int tid = threadIdx.x;
    const int l0  = blockIdx.x * 32;
    const int d0  = blockIdx.y * 128;

    for (int i = tid; i < 32 * FO; i += 256)
        Ss[i >> 6][i & 63] = g_S[(l0 + (i >> 6)) * FO + (i & 63)];
    for (int i = tid; i < FO * 128; i += 256)
        Ws[i >> 7][i & 127] = Wout[(i >> 7) * DM + d0 + (i & 127)];
    __syncthreads();

    const int dl  = tid & 127;
    const int lgp = tid >> 7;        // 0..1, 16 l's each
    float acc[16];
    #pragma unroll
    for (int i = 0; i < 16; i++) acc[i] = 0.0f;
    #pragma unroll
    for (int f = 0; f < FO; f++) {
        const float w = Ws[f][dl];
        #pragma unroll
        for (int i = 0; i < 16; i++) acc[i] += Ss[lgp * 16 + i][f] * w;
    }
    const int d = d0 + dl;
    const float ad = fabsf(deltas[d]);
    #pragma unroll
    for (int i = 0; i < 16; i++) {
        const int l = l0 + lgp * 16 + i;
        g_k[(size_t)d * LSEQ + l] = acc[i] * (expf(-t[l] * ad) + SHIFT_C);
    }
}

// ---------------- per-channel kernel spectrum (scrambled order) -------------
__global__ void __launch_bounds__(FFT_THREADS, 1)
kf_kernel() {
    extern __shared__ float2 sm[];
    float2* data = sm;
    float2* tw   = sm + NFFT;
    const int tid = threadIdx.x;
    const int d   = blockIdx.x;

    for (int i = tid; i < NQ; i += FFT_THREADS) tw[i] = g_tw[i];
    const float* krow = g_k + (size_t)d * LSEQ;
    for (int i = tid; i < LSEQ; i += FFT_THREADS) {
        data[i]        = make_float2(krow[i], 0.0f);
        data[i + LSEQ] = make_float2(0.0f, 0.0f);
    }
    __syncthreads();
    fft4_fwd(data, tw, tid);
    float2* out = g_Kf + (size_t)d * NFFT;
    for (int i = tid; i < NFFT; i += FFT_THREADS) out[i] = data[i];
}

// ---------------- conv: pack (b, b+1) as real/imag, fwd, mul, inv -----------
__global__ void __launch_bounds__(FFT_THREADS, 1)
conv_kernel(const float* __restrict__ x, const float* __restrict__ Dbias,
            float* __restrict__ out) {
    extern __shared__ float2 sm[];
    float2* data = sm;
    float2* tw   = sm + NFFT;
    const int tid = threadIdx.x;
    const int d   = blockIdx.x;
    const int p   = blockIdx.y;                 // batch pair

    const float* u0 = x + ((size_t)(2*p)     * DM + d) * LSEQ;
    const float* u1 = x + ((size_t)(2*p + 1) * DM + d) * LSEQ;

    for (int i = tid; i < NQ; i += FFT_THREADS) tw[i] = g_tw[i];
    for (int i = tid; i < LSEQ; i += FFT_THREADS) {
        data[i]        = make_float2(u0[i], u1[i]);
        data[i + LSEQ] = make_float2(0.0f, 0.0f);
    }
    __syncthreads();

    fft4_fwd(data, tw, tid);

    const float2* kf = g_Kf + (size_t)d * NFFT;
    for (int i = tid; i < NFFT; i += FFT_THREADS) data[i] = cmul(data[i], kf[i]);
    __syncthreads();

    fft4_inv(data, tw, tid);

    const float Dd = Dbias[d];
    float* o0 = out + ((size_t)(2*p)     * DM + d) * LSEQ;
    float* o1 = out + ((size_t)(2*p + 1) * DM + d) * LSEQ;
    for (int i = tid; i < LSEQ; i += FFT_THREADS) {
        const float2 w = data[i];
        o0[i] = w.x + Dd * u0[i];
        o1[i] = w.y + Dd * u1[i];
    }
}

// ---------------- launch ----------------------------------------------------
// Input order (metadata): x, z, t, freq, W1, b1, W2, b2, W3, b3, Wout, deltas, D
extern "C" void kernel_launch(void* const* d_in, const int* in_sizes, int n_in,
                              void* d_out, int out_size) {
    (void)in_sizes; (void)n_in; (void)out_size;
    const float* x      = (const float*)d_in[0];
    const float* z      = (const float*)d_in[1];
    const float* t      = (const float*)d_in[2];
    const float* freq   = (const float*)d_in[3];
    const float* W1     = (const float*)d_in[4];
    const float* b1     = (const float*)d_in[5];
    const float* W2     = (const float*)d_in[6];
    const float* b2     = (const float*)d_in[7];
    const float* W3     = (const float*)d_in[8];
    const float* b3     = (const float*)d_in[9];
    const float* Wout   = (const float*)d_in[10];
    const float* deltas = (const float*)d_in[11];
    const float* Dbias  = (const float*)d_in[12];
    float* out = (float*)d_out;

    // idempotent; safe under graph capture (not a stream-ordered op)
    cudaFuncSetAttribute(kf_kernel,   cudaFuncAttributeMaxDynamicSharedMemorySize, SMEM_BYTES);
    cudaFuncSetAttribute(conv_kernel, cudaFuncAttributeMaxDynamicSharedMemorySize, SMEM_BYTES);

    twiddle_init_kernel<<<NQ / 512, 512>>>();
    mlp_kernel<<<LSEQ / 4, 256>>>(z, freq, W1, b1, W2, b2, W3, b3);
    filt_kernel<<<dim3(LSEQ / 32, DM / 128), 256>>>(Wout, t, deltas);
    kf_kernel<<<DM, FFT_THREADS, SMEM_BYTES>>>();
    conv_kernel<<<dim3(DM, 2), FFT_THREADS, SMEM_BYTES>>>(x, Dbias, out);
}

// round 2
// speedup vs baseline: 2.2946x; 2.2946x over previous
#include <cuda_runtime.h>
#include <math.h>

// Problem constants
#define LSEQ 8192
#define NFFT 16384          // 2*LSEQ = 4^7
#define DM   768
#define EMB  33
#define FO   64
#define SHIFT_C 0.05f
#define NT   512            // FFT threads per CTA

// Padded shared layout: +4 float2 per 64 float2 (32B per 512B) -> conflict-free strided passes
#define PHYS(i) ((i) + (((i) >> 6) << 2))
#define DPAD 17408                                   // PHYS(16383)=17403, round up
#define NTW  4096                                    // N/4 twiddles
#define SMEM_BYTES ((DPAD + NTW) * (int)sizeof(float2))   // 172032 B

// ---------------- scratch (device globals: no allocations allowed) ----------
__device__ float  g_S[LSEQ * FO];                       // post-MLP activations
__device__ float  g_k[DM * LSEQ];                       // filter k[d][l]
__device__ __align__(16) float2 g_Kf[(size_t)DM * NFFT];// scrambled spectrum * (1/N)
__device__ float2 g_tw[NTW];                            // W_N^t, t < N/4

// ---------------- complex helpers ----------------
__device__ __forceinline__ float2 cadd(float2 a, float2 b){ return make_float2(a.x+b.x, a.y+b.y); }
__device__ __forceinline__ float2 csub(float2 a, float2 b){ return make_float2(a.x-b.x, a.y-b.y); }
__device__ __forceinline__ float2 cmul(float2 a, float2 b){
    return make_float2(a.x*b.x - a.y*b.y, a.x*b.y + a.y*b.x);
}
__device__ __forceinline__ float2 conjf2(float2 a){ return make_float2(a.x, -a.y); }

// radix-4 DIF forward core (no twiddle): a = F4 x, W4 = e^{-i pi/2}
__device__ __forceinline__ void bf4f(float2 x0, float2 x1, float2 x2, float2 x3,
                                     float2& a0, float2& a1, float2& a2, float2& a3) {
    float2 t0 = cadd(x0, x2), t1 = csub(x0, x2);
    float2 t2 = cadd(x1, x3), t3 = csub(x1, x3);
    float2 mi = make_float2(t3.y, -t3.x);              // -i * t3
    a0 = cadd(t0, t2);
    a1 = cadd(t1, mi);
    a2 = csub(t0, t2);
    a3 = csub(t1, mi);
}
// radix-4 inverse core (unscaled): x = conj(F4) a = 4*F4^{-1} a
__device__ __forceinline__ void bf4i(float2 x0, float2 x1, float2 x2, float2 x3,
                                     float2& a0, float2& a1, float2& a2, float2& a3) {
    float2 t0 = cadd(x0, x2), t1 = csub(x0, x2);
    float2 t2 = cadd(x1, x3), t3 = csub(x1, x3);
    float2 pi = make_float2(-t3.y, t3.x);              // +i * t3
    a0 = cadd(t0, t2);
    a1 = cadd(t1, pi);
    a2 = csub(t0, t2);
    a3 = csub(t1, pi);
}

// ---------------- register radix-16 cores (two fused radix-4 DIF stages) ----
// spanLo = 1<<LS; elements x[r] live at array position b + r*spanLo.
template<int LS>
__device__ __forceinline__ void fft16_fwd(float2* x, const float2* tw, int j) {
    const int step16 = NFFT >> (LS + 4);
    const int step4  = NFFT >> (LS + 2);
    float2 y[16];
    #pragma unroll
    for (int c = 0; c < 4; c++) {
        float2 a0, a1, a2, a3;
        bf4f(x[c], x[c+4], x[c+8], x[c+12], a0, a1, a2, a3);
        float2 w1 = tw[(j + (c << LS)) * step16];
        float2 w2 = cmul(w1, w1), w3 = cmul(w2, w1);
        y[c]    = a0;
        y[c+4]  = cmul(a1, w1);
        y[c+8]  = cmul(a2, w2);
        y[c+12] = cmul(a3, w3);
    }
    float2 w1 = tw[j * step4];
    float2 w2 = cmul(w1, w1), w3 = cmul(w2, w1);
    #pragma unroll
    for (int m = 0; m < 4; m++) {
        float2 a0, a1, a2, a3;
        bf4f(y[4*m], y[4*m+1], y[4*m+2], y[4*m+3], a0, a1, a2, a3);
        x[4*m]   = a0;
        x[4*m+1] = cmul(a1, w1);
        x[4*m+2] = cmul(a2, w2);
        x[4*m+3] = cmul(a3, w3);
    }
}

template<int LS>
__device__ __forceinline__ void fft16_inv(float2* x, const float2* tw, int j) {
    const int step16 = NFFT >> (LS + 4);
    const int step4  = NFFT >> (LS + 2);
    float2 wl1 = conjf2(tw[j * step4]);
    float2 wl2 = cmul(wl1, wl1), wl3 = cmul(wl2, wl1);
    float2 y[16];
    #pragma unroll
    for (int m = 0; m < 4; m++) {
        float2 z0 = x[4*m];
        float2 z1 = cmul(x[4*m+1], wl1);
        float2 z2 = cmul(x[4*m+2], wl2);
        float2 z3 = cmul(x[4*m+3], wl3);
        bf4i(z0, z1, z2, z3, y[4*m], y[4*m+1], y[4*m+2], y[4*m+3]);
    }
    #pragma unroll
    for (int c = 0; c < 4; c++) {
        float2 wh1 = conjf2(tw[(j + (c << LS)) * step16]);
        float2 wh2 = cmul(wh1, wh1), wh3 = cmul(wh2, wh1);
        float2 z0 = y[c];
        float2 z1 = cmul(y[c+4],  wh1);
        float2 z2 = cmul(y[c+8],  wh2);
        float2 z3 = cmul(y[c+12], wh3);
        bf4i(z0, z1, z2, z3, x[c], x[c+4], x[c+8], x[c+12]);
    }
}

// ---------------- shared-memory fused passes --------------------------------
template<int LS>
__device__ __forceinline__ void pass_fwd(float2* d, const float2* tw, int tid) {
    #pragma unroll
    for (int k = 0; k < 2; k++) {
        const int c = tid + k * NT;
        const int j = c & ((1 << LS) - 1);
        const int g = c >> LS;
        const int b = (g << (LS + 4)) + j;
        float2 x[16];
        #pragma unroll
        for (int r = 0; r < 16; r++) x[r] = d[PHYS(b + (r << LS))];
        fft16_fwd<LS>(x, tw, j);
        #pragma unroll
        for (int r = 0; r < 16; r++) d[PHYS(b + (r << LS))] = x[r];
    }
    __syncthreads();
}

template<int LS>
__device__ __forceinline__ void pass_inv(float2* d, const float2* tw, int tid) {
    #pragma unroll
    for (int k = 0; k < 2; k++) {
        const int c = tid + k * NT;
        const int j = c & ((1 << LS) - 1);
        const int g = c >> LS;
        const int b = (g << (LS + 4)) + j;
        float2 x[16];
        #pragma unroll
        for (int r = 0; r < 16; r++) x[r] = d[PHYS(b + (r << LS))];
        fft16_inv<LS>(x, tw, j);
        #pragma unroll
        for (int r = 0; r < 16; r++) d[PHYS(b + (r << LS))] = x[r];
    }
    __syncthreads();
}

// ---------------- twiddle init (double-precision sincospi) ------------------
__global__ void twiddle_init_kernel() {
    int t = blockIdx.x * blockDim.x + threadIdx.x;
    if (t < NTW) {
        double s, c;
        sincospi(-2.0 * (double)t / (double)NFFT, &s, &c);
        g_tw[t] = make_float2((float)c, (float)s);
    }
}

// ---------------- filter MLP stages 1-3 -------------------------------------
__global__ void mlp_kernel(const float* __restrict__ z, const float* __restrict__ freq,
                           const float* __restrict__ W1, const float* __restrict__ b1,
                           const float* __restrict__ W2, const float* __restrict__ b2,
                           const float* __restrict__ W3, const float* __restrict__ b3) {
    __shared__ float zs[4][EMB];
    __shared__ float as[4][FO];
    __shared__ float bs[4][FO];
    const int tid = threadIdx.x;
    const int lg  = tid >> 6;
    const int f   = tid & 63;
    const int l   = blockIdx.x * 4 + lg;

    if (f < EMB) zs[lg][f] = z[l * EMB + f];
    __syncthreads();

    const float fr = freq[f];

    float acc = b1[f];
    #pragma unroll
    for (int e = 0; e < EMB; e++) acc += zs[lg][e] * W1[e * FO + f];
    as[lg][f] = sinf(fr * acc);
    __syncthreads();

    acc = b2[f];
    #pragma unroll
    for (int e = 0; e < FO; e++) acc += as[lg][e] * W2[e * FO + f];
    bs[lg][f] = sinf(fr * acc);
    __syncthreads();

    acc = b3[f];
    #pragma unroll
    for (int e = 0; e < FO; e++) acc += bs[lg][e] * W3[e * FO + f];
    g_S[l * FO + f] = sinf(fr * acc);
}

// ---------------- output projection + exponential modulation ----------------
__global__ void filt_kernel(const float* __restrict__ Wout, const float* __restrict__ t,
                            const float* __restrict__ deltas) {
    __shared__ float Ss[32][FO];
    __shared__ float Ws[FO][128];
    const int tid = threadIdx.x;
    const int l0  = blockIdx.x * 32;
    const int d0  = blockIdx.y * 128;

    for (int i = tid; i < 32 * FO; i += 256)
        Ss[i >> 6][i & 63] = g_S[(l0 + (i >> 6)) * FO + (i & 63)];
    for (int i = tid; i < FO * 128; i += 256)
        Ws[i >> 7][i & 127] = Wout[(i >> 7) * DM + d0 + (i & 127)];
    __syncthreads();

    const int dl  = tid & 127;
    const int lgp = tid >> 7;
    float acc[16];
    #pragma unroll
    for (int i = 0; i < 16; i++) acc[i] = 0.0f;
    #pragma unroll
    for (int f = 0; f < FO; f++) {
        const float w = Ws[f][dl];
        #pragma unroll
        for (int i = 0; i < 16; i++) acc[i] += Ss[lgp * 16 + i][f] * w;
    }
    const int d = d0 + dl;
    const float ad = fabsf(deltas[d]);
    #pragma unroll
    for (int i = 0; i < 16; i++) {
        const int l = l0 + lgp * 16 + i;
        g_k[(size_t)d * LSEQ + l] = acc[i] * (expf(-t[l] * ad) + SHIFT_C);
    }
}

// ---------------- kernel spectrum: 3 smem passes + direct global store ------
__global__ void __launch_bounds__(NT, 1)
kf_kernel() {
    extern __shared__ float2 sm[];
    float2* d  = sm;
    float2* tw = sm + DPAD;
    const int tid = threadIdx.x;
    const int ch  = blockIdx.x;

    for (int i = tid; i < NTW; i += NT) tw[i] = g_tw[i];
    __syncthreads();

    const float* krow = g_k + (size_t)ch * LSEQ;

    // P1: stages (6,5), LS=10, input fused from global (second half zero)
    #pragma unroll
    for (int k = 0; k < 2; k++) {
        const int j = tid + k * NT;
        float2 x[16];
        #pragma unroll
        for (int r = 0; r < 16; r++) {
            x[r] = (r < 8) ? make_float2(krow[j + (r << 10)], 0.0f)
                           : make_float2(0.0f, 0.0f);
        }
        fft16_fwd<10>(x, tw, j);
        #pragma unroll
        for (int r = 0; r < 16; r++) d[PHYS(j + (r << 10))] = x[r];
    }
    __syncthreads();

    pass_fwd<6>(d, tw, tid);   // stages (4,3)
    pass_fwd<2>(d, tw, tid);   // stages (2,1)

    // P4: stage 0 (twiddle = 1) + 1/N scale, store straight to g_Kf
    float2* out = g_Kf + (size_t)ch * NFFT;
    const float sc = 1.0f / (float)NFFT;
    #pragma unroll
    for (int k = 0; k < 8; k++) {
        const int q = tid + k * NT;
        const int p = PHYS(4 * q);
        float4 lo = *reinterpret_cast<float4*>(&d[p]);
        float4 hi = *reinterpret_cast<float4*>(&d[p + 2]);
        float2 a0, a1, a2, a3;
        bf4f(make_float2(lo.x, lo.y), make_float2(lo.z, lo.w),
             make_float2(hi.x, hi.y), make_float2(hi.z, hi.w), a0, a1, a2, a3);
        float4 o01 = make_float4(a0.x * sc, a0.y * sc, a1.x * sc, a1.y * sc);
        float4 o23 = make_float4(a2.x * sc, a2.y * sc, a3.x * sc, a3.y * sc);
        reinterpret_cast<float4*>(out)[2 * q]     = o01;
        reinterpret_cast<float4*>(out)[2 * q + 1] = o23;
    }
}

// ---------------- conv: fwd, fused stage0*Kf*inv-stage0, inv ----------------
__global__ void __launch_bounds__(NT, 1)
conv_kernel(const float* __restrict__ x, const float* __restrict__ Dbias,
            float* __restrict__ out) {
    extern __shared__ float2 sm[];
    float2* d  = sm;
    float2* tw = sm + DPAD;
    const int tid = threadIdx.x;
    const int ch  = blockIdx.x;
    const int p   = blockIdx.y;                   // batch pair

    const float* u0 = x + ((size_t)(2*p)     * DM + ch) * LSEQ;
    const float* u1 = x + ((size_t)(2*p + 1) * DM + ch) * LSEQ;

    for (int i = tid; i < NTW; i += NT) tw[i] = g_tw[i];
    __syncthreads();

    // P1 fwd: stages (6,5), input fused from global (pack u0 + i*u1, pad zeros)
    #pragma unroll
    for (int k = 0; k < 2; k++) {
        const int j = tid + k * NT;
        float2 xv[16];
        #pragma unroll
        for (int r = 0; r < 16; r++) {
            if (r < 8) {
                const int i = j + (r << 10);
                xv[r] = make_float2(u0[i], u1[i]);
            } else {
                xv[r] = make_float2(0.0f, 0.0f);
            }
        }
        fft16_fwd<10>(xv, tw, j);
        #pragma unroll
        for (int r = 0; r < 16; r++) d[PHYS(j + (r << 10))] = xv[r];
    }
    __syncthreads();

    pass_fwd<6>(d, tw, tid);   // stages (4,3)
    pass_fwd<2>(d, tw, tid);   // stages (2,1)

    // Combined: fwd stage 0 -> pointwise * Kf -> inv stage 0, all in registers
    const float2* kf = g_Kf + (size_t)ch * NFFT;
    #pragma unroll
    for (int k = 0; k < 8; k++) {
        const int q = tid + k * NT;
        const int pp = PHYS(4 * q);
        float4 lo = *reinterpret_cast<float4*>(&d[pp]);
        float4 hi = *reinterpret_cast<float4*>(&d[pp + 2]);
        float2 a0, a1, a2, a3;
        bf4f(make_float2(lo.x, lo.y), make_float2(lo.z, lo.w),
             make_float2(hi.x, hi.y), make_float2(hi.z, hi.w), a0, a1, a2, a3);
        const float4 k01 = reinterpret_cast<const float4*>(kf)[2 * q];
        const float4 k23 = reinterpret_cast<const float4*>(kf)[2 * q + 1];
        a0 = cmul(a0, make_float2(k01.x, k01.y));
        a1 = cmul(a1, make_float2(k01.z, k01.w));
        a2 = cmul(a2, make_float2(k23.x, k23.y));
        a3 = cmul(a3, make_float2(k23.z, k23.w));
        float2 z0, z1, z2, z3;
        bf4i(a0, a1, a2, a3, z0, z1, z2, z3);
        *reinterpret_cast<float4*>(&d[pp])     = make_float4(z0.x, z0.y, z1.x, z1.y);
        *reinterpret_cast<float4*>(&d[pp + 2]) = make_float4(z2.x, z2.y, z3.x, z3.y);
    }
    __syncthreads();

    pass_inv<2>(d, tw, tid);   // undo stages (1,2)
    pass_inv<6>(d, tw, tid);   // undo stages (3,4)

    // Final inv pass: stages (5,6), LS=10, fused residual + global store
    const float Dd = Dbias[ch];
    float* o0 = out + ((size_t)(2*p)     * DM + ch) * LSEQ;
    float* o1 = out + ((size_t)(2*p + 1) * DM + ch) * LSEQ;
    #pragma unroll
    for (int k = 0; k < 2; k++) {
        const int j = tid + k * NT;
        float2 xv[16];
        #pragma unroll
        for (int r = 0; r < 16; r++) xv[r] = d[PHYS(j + (r << 10))];
        fft16_inv<10>(xv, tw, j);
        #pragma unroll
        for (int r = 0; r < 8; r++) {
            const int i = j + (r << 10);
            o0[i] = xv[r].x + Dd * u0[i];
            o1[i] = xv[r].y + Dd * u1[i];
        }
    }
}

// ---------------- launch ----------------------------------------------------
// Input order (metadata): x, z, t, freq, W1, b1, W2, b2, W3, b3, Wout, deltas, D
extern "C" void kernel_launch(void* const* d_in, const int* in_sizes, int n_in,
                              void* d_out, int out_size) {
    (void)in_sizes; (void)n_in; (void)out_size;
    const float* x      = (const float*)d_in[0];
    const float* z      = (const float*)d_in[1];
    const float* t      = (const float*)d_in[2];
    const float* freq   = (const float*)d_in[3];
    const float* W1     = (const float*)d_in[4];
    const float* b1     = (const float*)d_in[5];
    const float* W2     = (const float*)d_in[6];
    const float* b2     = (const float*)d_in[7];
    const float* W3     = (const float*)d_in[8];
    const float* b3     = (const float*)d_in[9];
    const float* Wout   = (const float*)d_in[10];
    const float* deltas = (const float*)d_in[11];
    const float* Dbias  = (const float*)d_in[12];
    float* out = (float*)d_out;

    cudaFuncSetAttribute(kf_kernel,   cudaFuncAttributeMaxDynamicSharedMemorySize, SMEM_BYTES);
    cudaFuncSetAttribute(conv_kernel, cudaFuncAttributeMaxDynamicSharedMemorySize, SMEM_BYTES);

    twiddle_init_kernel<<<NTW / 512, 512>>>();
    mlp_kernel<<<LSEQ / 4, 256>>>(z, freq, W1, b1, W2, b2, W3, b3);
    filt_kernel<<<dim3(LSEQ / 32, DM / 128), 256>>>(Wout, t, deltas);
    kf_kernel<<<DM, NT, SMEM_BYTES>>>();
    conv_kernel<<<dim3(DM, 2), NT, SMEM_BYTES>>>(x, Dbias, out);
}